// round 12
// baseline (speedup 1.0000x reference)
#include <cuda_runtime.h>
#include <math.h>
#include <stdint.h>

// Problem constants
#define BB 2
#define SS 2048
#define CC 1024
#define HH 16
#define DD 64
#define NROW (BB*SS)          // 4096

// -------- scratch (allocation-free: __device__ globals) --------
__device__ float g_qh[(size_t)BB*HH*SS*DD];   // [B,H,S,D] (Q pre-scaled by 1/8)
__device__ float g_kh[(size_t)BB*HH*SS*DD];
__device__ float g_vh[(size_t)BB*HH*SS*DD];
__device__ float g_ot[(size_t)BB*SS*CC];      // attention output, [B,S,C]
__device__ float g_m [(size_t)BB*HH*SS];      // per-row final max
__device__ float g_il[(size_t)BB*HH*SS];      // per-row 1/sumexp

// ------------ tf32 helpers ------------
__device__ __forceinline__ float tf32f(float x) {
    uint32_t u;
    asm("cvt.rna.tf32.f32 %0, %1;" : "=r"(u) : "f"(x));
    return __uint_as_float(u);
}

// D += A(16x8) * B(8x8), tf32 inputs, f32 accumulate.
__device__ __forceinline__ void mma_tf32(float4& d, const uint32_t* a, const uint32_t* b) {
    asm volatile(
        "mma.sync.aligned.m16n8k8.row.col.f32.tf32.tf32.f32 "
        "{%0,%1,%2,%3}, {%4,%5,%6,%7}, {%8,%9}, {%0,%1,%2,%3};\n"
        : "+f"(d.x), "+f"(d.y), "+f"(d.z), "+f"(d.w)
        : "r"(a[0]), "r"(a[1]), "r"(a[2]), "r"(a[3]),
          "r"(b[0]), "r"(b[1]));
}

// ============================================================
// Projection GEMM (tf32 MMA): out[4096,1024] = (X @ W + bias) * out_scale
// Tile 128x128, BK=32, 8 warps as 2(M) x 4(N); warp tile 64x32.
// ============================================================
__global__ __launch_bounds__(256, 2)
void proj_kernel(const float* __restrict__ X, const float* __restrict__ W,
                 const float* __restrict__ bias, float* __restrict__ out,
                 int permute, float out_scale)
{
    __shared__ float As[128*36];   // As[m][k]
    __shared__ float Bs[32*136];   // Bs[k][n]

    const int tid  = threadIdx.x;
    const int lane = tid & 31;
    const int g    = lane >> 2;
    const int t    = lane & 3;
    const int w    = tid >> 5;
    const int wm   = w & 1;
    const int wn   = w >> 1;
    const int mBase = blockIdx.y * 128;
    const int nBase = blockIdx.x * 128;

    float4 acc[4][4];
#pragma unroll
    for (int i = 0; i < 4; i++)
#pragma unroll
        for (int j = 0; j < 4; j++) acc[i][j] = make_float4(0.f,0.f,0.f,0.f);

    for (int kt = 0; kt < CC; kt += 32) {
#pragma unroll
        for (int i = 0; i < 4; i++) {
            int f  = tid + i * 256;
            int r  = f >> 3;
            int c4 = f & 7;
            float4 v = *(const float4*)(X + (size_t)(mBase + r) * CC + kt + c4 * 4);
            float4 cv = make_float4(tf32f(v.x), tf32f(v.y), tf32f(v.z), tf32f(v.w));
            *(float4*)&As[r*36 + c4*4] = cv;
        }
#pragma unroll
        for (int i = 0; i < 4; i++) {
            int f = tid + i * 256;
            int r = f >> 5;
            int c = f & 31;
            float4 v = *(const float4*)(W + (size_t)(kt + r) * CC + nBase + c * 4);
            float4 cv = make_float4(tf32f(v.x), tf32f(v.y), tf32f(v.z), tf32f(v.w));
            *(float4*)&Bs[r*136 + c*4] = cv;
        }
        __syncthreads();

#pragma unroll
        for (int ks = 0; ks < 32; ks += 8) {
            uint32_t a[4][4], b[4][2];
#pragma unroll
            for (int i = 0; i < 4; i++) {
                int r0 = wm*64 + i*16 + g;
                a[i][0] = __float_as_uint(As[ r0      *36 + ks+t  ]);
                a[i][1] = __float_as_uint(As[(r0 + 8) *36 + ks+t  ]);
                a[i][2] = __float_as_uint(As[ r0      *36 + ks+t+4]);
                a[i][3] = __float_as_uint(As[(r0 + 8) *36 + ks+t+4]);
            }
#pragma unroll
            for (int j = 0; j < 4; j++) {
                int c = wn*32 + j*8 + g;
                b[j][0] = __float_as_uint(Bs[(ks+t  )*136 + c]);
                b[j][1] = __float_as_uint(Bs[(ks+t+4)*136 + c]);
            }
#pragma unroll
            for (int i = 0; i < 4; i++)
#pragma unroll
                for (int j = 0; j < 4; j++)
                    mma_tf32(acc[i][j], a[i], b[j]);
        }
        __syncthreads();
    }

#pragma unroll
    for (int i = 0; i < 4; i++) {
        int r0 = mBase + wm*64 + i*16 + g;
        int r1 = r0 + 8;
#pragma unroll
        for (int j = 0; j < 4; j++) {
            int col = nBase + wn*32 + j*8 + 2*t;
            float b0 = bias[col], b1 = bias[col+1];
            float2 v0 = make_float2((acc[i][j].x + b0) * out_scale, (acc[i][j].y + b1) * out_scale);
            float2 v1 = make_float2((acc[i][j].z + b0) * out_scale, (acc[i][j].w + b1) * out_scale);
            if (permute) {
                int h = col >> 6, d = col & 63;
                int bb0 = r0 / SS, s0 = r0 % SS;
                int bb1 = r1 / SS, s1 = r1 % SS;
                *(float2*)(out + ((size_t)(bb0*HH + h)*SS + s0)*DD + d) = v0;
                *(float2*)(out + ((size_t)(bb1*HH + h)*SS + s1)*DD + d) = v1;
            } else {
                *(float2*)(out + (size_t)r0 * CC + col) = v0;
                *(float2*)(out + (size_t)r1 * CC + col) = v1;
            }
        }
    }
}

// ============================================================
// attn1: per (b,h,q-tile=128): S = Qs@K^T (Q pre-scaled), write RAW
// scores into the attn output buffer (scratch until attn2 rewrites),
// track online per-row (m,l); reduce and store (m, 1/l) to gmem.
// 8 warps as 4(m) x 2(n), warp tile 32x32. Smem 52KB -> 3 CTAs.
// ============================================================
#define QS_P 68
#define KS_P 68
#define A1_FLOATS (128*QS_P + 64*KS_P)   // 13056 floats = 52,224 B

__global__ __launch_bounds__(256, 3)
void attn1_kernel(float* __restrict__ attn)
{
    extern __shared__ float sm[];
    float* Qs = sm;
    float* Ks = sm + 128*QS_P;

    const int tid  = threadIdx.x;
    const int lane = tid & 31;
    const int g    = lane >> 2;
    const int t    = lane & 3;
    const int w    = tid >> 5;
    const int wm   = w & 3;
    const int wn   = w >> 2;
    const int qBase = blockIdx.x * 128;
    const int bh    = blockIdx.y;

    const float* Qg = g_qh + (size_t)bh * SS * DD;
    const float* Kg = g_kh + (size_t)bh * SS * DD;
    float* attn_bh  = attn + (size_t)bh * SS * SS;

    // Load Q tile (pre-scaled by 1/8) -> Qs[q][d]
#pragma unroll
    for (int i = 0; i < 8; i++) {
        int f  = tid + i * 256;
        int r  = f >> 4;
        int c4 = f & 15;
        float4 v = *(const float4*)(Qg + (size_t)(qBase + r) * DD + c4 * 4);
        float4 cv = make_float4(tf32f(v.x), tf32f(v.y), tf32f(v.z), tf32f(v.w));
        *(float4*)&Qs[r*QS_P + c4*4] = cv;
    }

    // K prefetch registers (tile 0)
    const int kf_r  = tid >> 4;       // 0..15 (x4 via i)
    const int kf_c4 = tid & 15;
    float4 kp[4];
#pragma unroll
    for (int i = 0; i < 4; i++)
        kp[i] = *(const float4*)(Kg + (size_t)(kf_r + i*16) * DD + kf_c4 * 4);

    float m_run[4], l_run[4];
#pragma unroll
    for (int i = 0; i < 4; i++) { m_run[i] = -1e30f; l_run[i] = 0.0f; }

    for (int s0 = 0; s0 < SS; s0 += 64) {
        __syncthreads();             // Ks writable
#pragma unroll
        for (int i = 0; i < 4; i++) {
            int r = kf_r + i*16;
            float4 cv = make_float4(tf32f(kp[i].x), tf32f(kp[i].y), tf32f(kp[i].z), tf32f(kp[i].w));
            *(float4*)&Ks[r*KS_P + kf_c4*4] = cv;
        }
        __syncthreads();

        // prefetch next K tile while MMAing this one
        int sn = (s0 + 64 < SS) ? s0 + 64 : 0;
#pragma unroll
        for (int i = 0; i < 4; i++)
            kp[i] = *(const float4*)(Kg + (size_t)(sn + kf_r + i*16) * DD + kf_c4 * 4);

        float4 accs[2][4];
#pragma unroll
        for (int i = 0; i < 2; i++)
#pragma unroll
            for (int j = 0; j < 4; j++) accs[i][j] = make_float4(0.f,0.f,0.f,0.f);

#pragma unroll
        for (int dk = 0; dk < 64; dk += 8) {
            uint32_t a[2][4], b[4][2];
#pragma unroll
            for (int i = 0; i < 2; i++) {
                int r0 = wm*32 + i*16 + g;
                a[i][0] = __float_as_uint(Qs[ r0     *QS_P + dk+t  ]);
                a[i][1] = __float_as_uint(Qs[(r0 + 8)*QS_P + dk+t  ]);
                a[i][2] = __float_as_uint(Qs[ r0     *QS_P + dk+t+4]);
                a[i][3] = __float_as_uint(Qs[(r0 + 8)*QS_P + dk+t+4]);
            }
#pragma unroll
            for (int j = 0; j < 4; j++) {
                int c = wn*32 + j*8 + g;
                b[j][0] = __float_as_uint(Ks[c*KS_P + dk+t  ]);
                b[j][1] = __float_as_uint(Ks[c*KS_P + dk+t+4]);
            }
#pragma unroll
            for (int i = 0; i < 2; i++)
#pragma unroll
                for (int j = 0; j < 4; j++)
                    mma_tf32(accs[i][j], a[i], b[j]);
        }

        // online stats + raw score write (scores already scaled via Q)
#pragma unroll
        for (int i = 0; i < 2; i++) {
            int r0 = wm*32 + i*16 + g;
#pragma unroll
            for (int h = 0; h < 2; h++) {
                float v[8];
#pragma unroll
                for (int j = 0; j < 4; j++) {
                    v[2*j]   = h ? accs[i][j].z : accs[i][j].x;
                    v[2*j+1] = h ? accs[i][j].w : accs[i][j].y;
                }
                int ri = i*2 + h;
                float mt = v[0];
#pragma unroll
                for (int c = 1; c < 8; c++) mt = fmaxf(mt, v[c]);
                float mn = fmaxf(m_run[ri], mt);
                float s = 0.0f;
#pragma unroll
                for (int c = 0; c < 8; c++) s += __expf(v[c] - mn);
                l_run[ri] = l_run[ri] * __expf(m_run[ri] - mn) + s;
                m_run[ri] = mn;
            }
#pragma unroll
            for (int j = 0; j < 4; j++) {
                int colL = wn*32 + j*8 + 2*t;
                *(float2*)&attn_bh[(size_t)(qBase + r0    ) * SS + s0 + colL] =
                    make_float2(accs[i][j].x, accs[i][j].y);
                *(float2*)&attn_bh[(size_t)(qBase + r0 + 8) * SS + s0 + colL] =
                    make_float2(accs[i][j].z, accs[i][j].w);
            }
        }
    }

    // Cross-thread reduction (8 thr/row), then (m, 1/l) -> gmem
    float* redm = Qs;                // reuse (10 floats/row)
    float* redl = Qs + 128*10;
    const int slot = wn*4 + t;
    __syncthreads();
#pragma unroll
    for (int i = 0; i < 2; i++)
#pragma unroll
        for (int h = 0; h < 2; h++) {
            int row = wm*32 + i*16 + h*8 + g;
            redm[row*10 + slot] = m_run[i*2+h];
            redl[row*10 + slot] = l_run[i*2+h];
        }
    __syncthreads();
    if (tid < 128) {
        int row = tid;
        float mf = -1e30f;
#pragma unroll
        for (int s = 0; s < 8; s++) mf = fmaxf(mf, redm[row*10 + s]);
        float lf = 0.0f;
#pragma unroll
        for (int s = 0; s < 8; s++) lf += redl[row*10 + s] * __expf(redm[row*10 + s] - mf);
        g_m [(size_t)bh * SS + qBase + row] = mf;
        g_il[(size_t)bh * SS + qBase + row] = 1.0f / lf;
    }
}

// ============================================================
// attn2: read raw S, p = exp(s-m)*invl, overwrite attn with probs,
// stage tf32 P, O += P@V.  No Q/K work at all.  Smem 54KB -> 3 CTAs.
// 8 warps as 4(m) x 2(n); PV warp tile 32q x 32d.
// ============================================================
#define PS_P 68
#define VS_P 72
#define PS_OFF 0
#define VS_OFF (128*PS_P)
#define ML_OFF (VS_OFF + 64*VS_P)
#define A2_FLOATS (ML_OFF + 256)    // 13568 floats = 54,272 B

__global__ __launch_bounds__(256, 3)
void attn2_kernel(float* __restrict__ attn, float* __restrict__ o_tmp)
{
    extern __shared__ float sm[];
    float* Ps = sm + PS_OFF;
    float* Vs = sm + VS_OFF;
    float* ml = sm + ML_OFF;

    const int tid  = threadIdx.x;
    const int lane = tid & 31;
    const int g    = lane >> 2;
    const int t    = lane & 3;
    const int w    = tid >> 5;
    const int wm   = w & 3;
    const int wn   = w >> 2;
    const int qBase = blockIdx.x * 128;
    const int bh    = blockIdx.y;

    const float* Vg = g_vh + (size_t)bh * SS * DD;
    float* attn_bh  = attn + (size_t)bh * SS * SS;

    // Row stats into smem
    if (tid < 128) {
        ml[tid*2    ] = g_m [(size_t)bh * SS + qBase + tid];
        ml[tid*2 + 1] = g_il[(size_t)bh * SS + qBase + tid];
    }

    // V prefetch (tile 0)
    const int vf_r  = tid >> 4;
    const int vf_c4 = tid & 15;
    float4 vp[4];
#pragma unroll
    for (int i = 0; i < 4; i++)
        vp[i] = *(const float4*)(Vg + (size_t)(vf_r + i*16) * DD + vf_c4 * 4);

    float4 acc_o[2][4];
#pragma unroll
    for (int i = 0; i < 2; i++)
#pragma unroll
        for (int j = 0; j < 4; j++) acc_o[i][j] = make_float4(0.f,0.f,0.f,0.f);

    __syncthreads();   // ml ready

    for (int s0 = 0; s0 < SS; s0 += 64) {
        // V tile -> Vs[s][d]
#pragma unroll
        for (int i = 0; i < 4; i++) {
            int r = vf_r + i*16;
            float4 cv = make_float4(tf32f(vp[i].x), tf32f(vp[i].y), tf32f(vp[i].z), tf32f(vp[i].w));
            *(float4*)&Vs[r*VS_P + vf_c4*4] = cv;
        }
        // Raw S -> probs: gmem rewrite + tf32 staging in Ps[q][s]
#pragma unroll
        for (int i = 0; i < 8; i++) {
            int f  = tid + i * 256;
            int r  = f >> 4;
            int c4 = f & 15;
            float* gp = attn_bh + (size_t)(qBase + r) * SS + s0 + c4 * 4;
            float4 s4 = *(float4*)gp;
            float m  = ml[r*2], il = ml[r*2+1];
            float4 p4;
            p4.x = __expf(s4.x - m) * il;
            p4.y = __expf(s4.y - m) * il;
            p4.z = __expf(s4.z - m) * il;
            p4.w = __expf(s4.w - m) * il;
            *(float4*)gp = p4;
            float4 c4v = make_float4(tf32f(p4.x), tf32f(p4.y), tf32f(p4.z), tf32f(p4.w));
            *(float4*)&Ps[r*PS_P + c4*4] = c4v;
        }
        __syncthreads();

        // prefetch next V tile
        int sn = (s0 + 64 < SS) ? s0 + 64 : 0;
#pragma unroll
        for (int i = 0; i < 4; i++)
            vp[i] = *(const float4*)(Vg + (size_t)(sn + vf_r + i*16) * DD + vf_c4 * 4);

        // O += P @ V
#pragma unroll
        for (int sk = 0; sk < 64; sk += 8) {
            uint32_t a[2][4], b[4][2];
#pragma unroll
            for (int i = 0; i < 2; i++) {
                int r0 = wm*32 + i*16 + g;
                a[i][0] = __float_as_uint(Ps[ r0     *PS_P + sk+t  ]);
                a[i][1] = __float_as_uint(Ps[(r0 + 8)*PS_P + sk+t  ]);
                a[i][2] = __float_as_uint(Ps[ r0     *PS_P + sk+t+4]);
                a[i][3] = __float_as_uint(Ps[(r0 + 8)*PS_P + sk+t+4]);
            }
#pragma unroll
            for (int j = 0; j < 4; j++) {
                int c = wn*32 + j*8 + g;
                b[j][0] = __float_as_uint(Vs[(sk+t  )*VS_P + c]);
                b[j][1] = __float_as_uint(Vs[(sk+t+4)*VS_P + c]);
            }
#pragma unroll
            for (int i = 0; i < 2; i++)
#pragma unroll
                for (int j = 0; j < 4; j++)
                    mma_tf32(acc_o[i][j], a[i], b[j]);
        }
        __syncthreads();   // Ps/Vs reads done -> writable next iter
    }

    // Epilogue: O tile -> [B,S,C] scratch
    const int bb0 = bh >> 4, hh = bh & 15;
#pragma unroll
    for (int i = 0; i < 2; i++) {
        int r0 = qBase + wm*32 + i*16 + g;
#pragma unroll
        for (int j = 0; j < 4; j++) {
            int colL = wn*32 + j*8 + 2*t;
            *(float2*)(o_tmp + ((size_t)(bb0*SS + r0    )) * CC + hh*64 + colL) =
                make_float2(acc_o[i][j].x, acc_o[i][j].y);
            *(float2*)(o_tmp + ((size_t)(bb0*SS + r0 + 8)) * CC + hh*64 + colL) =
                make_float2(acc_o[i][j].z, acc_o[i][j].w);
        }
    }
}

// ============================================================
extern "C" void kernel_launch(void* const* d_in, const int* in_sizes, int n_in,
                              void* d_out, int out_size)
{
    const float* q  = (const float*)d_in[0];
    const float* k  = (const float*)d_in[1];
    const float* v  = (const float*)d_in[2];
    const float* wq = (const float*)d_in[3];
    const float* bq = (const float*)d_in[4];
    const float* wk = (const float*)d_in[5];
    const float* bk = (const float*)d_in[6];
    const float* wv = (const float*)d_in[7];
    const float* bv = (const float*)d_in[8];
    const float* wo = (const float*)d_in[9];
    const float* bo = (const float*)d_in[10];

    float* out  = (float*)d_out;                          // [B,S,C]
    float* attn = out + (size_t)BB * SS * CC;             // [B,H,S,S]

    float *qh, *kh, *vh, *ot;
    cudaGetSymbolAddress((void**)&qh, g_qh);
    cudaGetSymbolAddress((void**)&kh, g_kh);
    cudaGetSymbolAddress((void**)&vh, g_vh);
    cudaGetSymbolAddress((void**)&ot, g_ot);

    dim3 pgrid(CC / 128, NROW / 128);   // (8, 32)
    // Q projection carries the exact 1/8 attention scale (pow2 -> tf32-exact).
    proj_kernel<<<pgrid, 256>>>(q, wq, bq, qh, 1, 0.125f);
    proj_kernel<<<pgrid, 256>>>(k, wk, bk, kh, 1, 1.0f);
    proj_kernel<<<pgrid, 256>>>(v, wv, bv, vh, 1, 1.0f);

    size_t sh1 = (size_t)A1_FLOATS * sizeof(float);       // 52,224 B
    size_t sh2 = (size_t)A2_FLOATS * sizeof(float);       // 54,272 B
    cudaFuncSetAttribute(attn1_kernel,
                         cudaFuncAttributeMaxDynamicSharedMemorySize, (int)sh1);
    cudaFuncSetAttribute(attn2_kernel,
                         cudaFuncAttributeMaxDynamicSharedMemorySize, (int)sh2);
    attn1_kernel<<<dim3(SS / 128, BB * HH), 256, sh1>>>(attn);
    attn2_kernel<<<dim3(SS / 128, BB * HH), 256, sh2>>>(attn, ot);

    proj_kernel<<<pgrid, 256>>>(ot, wo, bo, out, 0, 1.0f);
}